// round 17
// baseline (speedup 1.0000x reference)
#include <cuda_runtime.h>
#include <cuda_fp16.h>

#define D_MODEL 512
#define NHEAD   8
#define HD      64
#define BATCH   2
#define SEQ     2048
#define LOG2E   1.4426950408889634f
#define QSCALE  (0.125f * LOG2E)     // 1/sqrt(64) * log2(e), folded into Q

// ---------------- scratch ----------------
__device__ __half g_Q[BATCH*NHEAD*SEQ*HD];   // pre-scaled by QSCALE
__device__ __half g_K[BATCH*NHEAD*SEQ*HD];
__device__ __half g_V[BATCH*NHEAD*SEQ*HD];
__device__ float  g_cp[BATCH*NHEAD*SEQ];     // coord proj ×LOG2E
// mask ×LOG2E, fp16, FRAGMENT-ORDERED: half2 index = q*1024 + kt*32 + t*8 + j
__device__ __half g_maskh[SEQ*SEQ];
__device__ __half g_xh[BATCH*SEQ*D_MODEL];   // x in fp16
__device__ __half g_wh[3*D_MODEL*D_MODEL];   // qkv_w in fp16

// ---------------- helpers ----------------
static __device__ __forceinline__ void mma_f16(float d[4], const unsigned a[4],
                                               unsigned b0, unsigned b1) {
    asm volatile("mma.sync.aligned.m16n8k16.row.col.f32.f16.f16.f32 "
                 "{%0,%1,%2,%3},{%4,%5,%6,%7},{%8,%9},{%0,%1,%2,%3};"
                 : "+f"(d[0]), "+f"(d[1]), "+f"(d[2]), "+f"(d[3])
                 : "r"(a[0]), "r"(a[1]), "r"(a[2]), "r"(a[3]), "r"(b0), "r"(b1));
}
static __device__ __forceinline__ unsigned smem_u32(const void* p) {
    return (unsigned)__cvta_generic_to_shared(p);
}
static __device__ __forceinline__ void ldsm_x4(unsigned& r0, unsigned& r1,
                                               unsigned& r2, unsigned& r3,
                                               unsigned addr) {
    asm volatile("ldmatrix.sync.aligned.m8n8.x4.shared.b16 {%0,%1,%2,%3}, [%4];"
                 : "=r"(r0), "=r"(r1), "=r"(r2), "=r"(r3) : "r"(addr));
}
static __device__ __forceinline__ void ldsm_x4t(unsigned& r0, unsigned& r1,
                                                unsigned& r2, unsigned& r3,
                                                unsigned addr) {
    asm volatile("ldmatrix.sync.aligned.m8n8.x4.trans.shared.b16 {%0,%1,%2,%3}, [%4];"
                 : "=r"(r0), "=r"(r1), "=r"(r2), "=r"(r3) : "r"(addr));
}
static __device__ __forceinline__ void cp16(unsigned dst, const void* src) {
    asm volatile("cp.async.cg.shared.global [%0], [%1], 16;"
                 :: "r"(dst), "l"(src));
}
static __device__ __forceinline__ unsigned exp2_pack(float a, float b) {
    __half2 h = h2exp2(__floats2half2_rn(a, b));   // ex2.approx.f16x2
    return *reinterpret_cast<unsigned*>(&h);
}
#define CP_COMMIT() asm volatile("cp.async.commit_group;")
#define CP_WAIT(n)  asm volatile("cp.async.wait_group %0;" :: "n"(n))

// ---------------- fused prep kernel (single launch) ----------------
#define MASK4 (SEQ*SEQ/4)
#define X4    (BATCH*SEQ*D_MODEL/4)
#define W4    (3*D_MODEL*D_MODEL/4)
#define NCP   (BATCH*NHEAD*SEQ)
#define PREP_TOT (MASK4 + X4 + W4 + NCP)

__global__ void prep_kernel(const float* __restrict__ mask,
                            const float* __restrict__ x,
                            const float* __restrict__ w,
                            const float* __restrict__ coords,
                            const float* __restrict__ rw) {
    int i = blockIdx.x * blockDim.x + threadIdx.x;
    if (i < MASK4) {
        float4 m = ((const float4*)mask)[i];
        int q = i >> 9;
        int c = (i & 511) * 4;
        int kt = c >> 6, r = c & 63;
        int j = r >> 3, t = (r & 7) >> 1;
        __half2* dst = (__half2*)g_maskh + q*1024 + kt*32 + j;
        dst[t*8]     = __floats2half2_rn(m.x*LOG2E, m.y*LOG2E);
        dst[(t+1)*8] = __floats2half2_rn(m.z*LOG2E, m.w*LOG2E);
        return;
    }
    i -= MASK4;
    if (i < X4) {
        float4 v = ((const float4*)x)[i];
        __half2* d = (__half2*)g_xh;
        d[i*2]     = __floats2half2_rn(v.x, v.y);
        d[i*2 + 1] = __floats2half2_rn(v.z, v.w);
        return;
    }
    i -= X4;
    if (i < W4) {
        float4 v = ((const float4*)w)[i];
        __half2* d = (__half2*)g_wh;
        d[i*2]     = __floats2half2_rn(v.x, v.y);
        d[i*2 + 1] = __floats2half2_rn(v.z, v.w);
        return;
    }
    i -= W4;
    if (i < NCP) {
        int n = i & (SEQ - 1);
        int h = (i >> 11) & 7;
        int b = i >> 14;
        const float* c = coords + (b*SEQ + n)*3;
        const float* wv = rw + h*3;
        g_cp[i] = (c[0]*wv[0] + c[1]*wv[1] + c[2]*wv[2]) * LOG2E;
    }
}

// ---------------- QKV GEMM: fp16 mma, cp.async double buffer ------------
#define GST 72
#define G_SMEM ((2*128*GST + 2*64*GST) * 2)

__global__ __launch_bounds__(256)
void qkv_gemm_kernel(const float* __restrict__ bias) {
    extern __shared__ __align__(16) char smraw[];
    __half* Xs = (__half*)smraw;
    __half* Ws = (__half*)smraw + 2*128*GST;
    const int m0 = blockIdx.y * 128, o0 = blockIdx.x * 64;
    const int tid = threadIdx.x, lane = tid & 31, warp = tid >> 5;
    const int g = lane >> 2, t = lane & 3, wm = warp * 16;
    const int lrow = lane & 15, lcol = (lane >> 4) << 3;

    const __half* xg = g_xh + (size_t)m0 * D_MODEL;
    const __half* wg = g_wh + (size_t)o0 * D_MODEL;

    auto issue = [&](int ch, int stg) {
        int kb = ch * 64;
        #pragma unroll
        for (int s = 0; s < 4; s++) {
            int slot = tid + s*256;
            int row = slot >> 3, c8 = slot & 7;
            cp16(smem_u32(&Xs[stg*128*GST + row*GST + c8*8]),
                 xg + (size_t)row*D_MODEL + kb + c8*8);
        }
        #pragma unroll
        for (int s = 0; s < 2; s++) {
            int slot = tid + s*256;
            int row = slot >> 3, c8 = slot & 7;
            cp16(smem_u32(&Ws[stg*64*GST + row*GST + c8*8]),
                 wg + (size_t)row*D_MODEL + kb + c8*8);
        }
    };

    float c[8][4] = {};
    issue(0, 0); CP_COMMIT();

    for (int ch = 0; ch < 8; ch++) {
        int cb = ch & 1;
        if (ch < 7) { issue(ch + 1, cb ^ 1); CP_COMMIT(); CP_WAIT(1); }
        else        { CP_WAIT(0); }
        __syncthreads();
        const __half* X = Xs + cb*128*GST;
        const __half* W = Ws + cb*64*GST;
        #pragma unroll
        for (int kk = 0; kk < 4; kk++) {
            unsigned a[4];
            ldsm_x4(a[0], a[1], a[2], a[3],
                    smem_u32(&X[(wm + lrow)*GST + kk*16 + lcol]));
            #pragma unroll
            for (int j = 0; j < 4; j++) {
                unsigned r0, r1, r2, r3;
                ldsm_x4(r0, r1, r2, r3,
                        smem_u32(&W[(j*16 + lrow)*GST + kk*16 + lcol]));
                mma_f16(c[2*j],     a, r0, r2);
                mma_f16(c[2*j + 1], a, r1, r3);
            }
        }
        __syncthreads();
    }

    const int which = o0 >> 9;
    const int h = (o0 >> 6) & 7;
    const float sc = (which == 0) ? QSCALE : 1.0f;
    __half* dstbase = (which == 0) ? g_Q : (which == 1 ? g_K : g_V);
    #pragma unroll
    for (int r = 0; r < 2; r++) {
        int m = m0 + wm + g + r*8;
        int b = m >> 11, n = m & 2047;
        __half* dst = dstbase + ((size_t)(b*NHEAD + h)*SEQ + n)*HD;
        #pragma unroll
        for (int j = 0; j < 8; j++) {
            int c0 = j*8 + t*2;
            float2 bi = *(const float2*)&bias[o0 + c0];
            *(__half2*)&dst[c0] = __floats2half2_rn(
                (c[j][r*2 + 0] + bi.x) * sc,
                (c[j][r*2 + 1] + bi.y) * sc);
        }
    }
}

// ---------------- flash attention: m=32/warp, 4 warps, 3-stage pipe ------
#define ST   72
#define NSTG 3
#define NT   (SEQ/64)
#define F_SMEM ((NSTG*128*ST)*2 + NSTG*64*4)   // 56064 bytes
#define ONE2 0x3C003C00u

__global__ __launch_bounds__(128, 2)
void flash_kernel(float* __restrict__ out) {
    extern __shared__ __align__(16) char smraw[];
    __half* KV  = (__half*)smraw;                  // NSTG * 128*ST
    float*  cpk = (float*)(KV + NSTG*128*ST);      // NSTG * 64

    const int b = blockIdx.z, h = blockIdx.y, q0 = blockIdx.x * 128;
    const int tid = threadIdx.x, lane = tid & 31, warp = tid >> 5;
    const int g = lane >> 2, t = lane & 3, wm = warp * 32;
    const int lrow = lane & 15, lcol = (lane >> 4) << 3;

    const size_t base = (size_t)(b*NHEAD + h) * SEQ;
    const __half* Qg  = g_Q + (base + q0) * HD;
    const __half* Kg  = g_K + base * HD;
    const __half* Vg  = g_V + base * HD;
    const float*  cpb = g_cp + base;

    // ---- stage Q through stage-0 smem, hoist fragments to registers ----
    #pragma unroll
    for (int s = 0; s < 8; s++) {
        int slot = tid + s*128;
        int row = slot >> 3, c8 = slot & 7;
        cp16(smem_u32(&KV[row*ST + c8*8]), Qg + (size_t)row*HD + c8*8);
    }
    CP_COMMIT(); CP_WAIT(0);
    __syncthreads();
    unsigned qa[2][4][4];
    #pragma unroll
    for (int mb = 0; mb < 2; mb++)
        #pragma unroll
        for (int kk = 0; kk < 4; kk++)
            ldsm_x4(qa[mb][kk][0], qa[mb][kk][1], qa[mb][kk][2], qa[mb][kk][3],
                    smem_u32(&KV[(wm + mb*16 + lrow)*ST + kk*16 + lcol]));
    __syncthreads();

    auto issue_kv = [&](int kt, int stg) {
        int k0 = kt * 64;
        __half* Kh = KV + stg*128*ST;
        __half* Vh = Kh + 64*ST;
        #pragma unroll
        for (int s = 0; s < 4; s++) {
            int slot = tid + s*128;
            int row = slot >> 3, c8 = slot & 7;
            cp16(smem_u32(&Kh[row*ST + c8*8]), Kg + (size_t)(k0+row)*HD + c8*8);
            cp16(smem_u32(&Vh[row*ST + c8*8]), Vg + (size_t)(k0+row)*HD + c8*8);
        }
        if (tid < 16) cp16(smem_u32(&cpk[stg*64 + tid*4]), cpb + k0 + tid*4);
    };

    issue_kv(0, 0); CP_COMMIT();
    issue_kv(1, 1); CP_COMMIT();

    float o[2][8][4] = {};
    float l_acc[2][4] = {};
    float m_st[2][2] = {{-1e30f,-1e30f},{-1e30f,-1e30f}};   // [mb][lo/hi]
    // fragment-ordered mask rows for this thread (4 rows: mb*16 + {g, g+8})
    const __half* mr[2][2];
    #pragma unroll
    for (int mb = 0; mb < 2; mb++) {
        mr[mb][0] = g_maskh + (size_t)(q0 + wm + mb*16 + g) * SEQ + t*16;
        mr[mb][1] = g_maskh + (size_t)(q0 + wm + mb*16 + g + 8) * SEQ + t*16;
    }

    for (int kt = 0; kt < NT; kt++) {
        const int stg = kt % NSTG;
        if (kt < NT - 1) { CP_WAIT(1); } else { CP_WAIT(0); }
        __syncthreads();
        if (kt + 2 < NT) { issue_kv(kt + 2, (kt + 2) % NSTG); CP_COMMIT(); }

        const __half* K = KV + stg*128*ST;
        const __half* V = K + 64*ST;
        const float*  cp = cpk + stg*64;

        // ---- S = Q·K^T (K frags shared across both m-blocks) ----
        float sreg[2][8][4] = {};
        #pragma unroll
        for (int kk = 0; kk < 4; kk++) {
            #pragma unroll
            for (int j = 0; j < 4; j++) {
                unsigned r0, r1, r2, r3;
                ldsm_x4(r0, r1, r2, r3,
                        smem_u32(&K[(j*16 + lrow)*ST + kk*16 + lcol]));
                #pragma unroll
                for (int mb = 0; mb < 2; mb++) {
                    mma_f16(sreg[mb][2*j],     qa[mb][kk], r0, r2);
                    mma_f16(sreg[mb][2*j + 1], qa[mb][kk], r1, r3);
                }
            }
        }

        // ---- bias: + mask(×LOG2E fp16, fragment-ordered) - cp_k ----
        #pragma unroll
        for (int mb = 0; mb < 2; mb++) {
            uint4 l0 = *(const uint4*)(mr[mb][0] + kt*64);
            uint4 l1 = *(const uint4*)(mr[mb][0] + kt*64 + 8);
            uint4 h0 = *(const uint4*)(mr[mb][1] + kt*64);
            uint4 h1 = *(const uint4*)(mr[mb][1] + kt*64 + 8);
            const unsigned* wl = (const unsigned*)&l0;
            const unsigned* wh = (const unsigned*)&h0;
            #pragma unroll
            for (int j = 0; j < 8; j++) {
                unsigned mwl = (j < 4) ? wl[j] : ((const unsigned*)&l1)[j-4];
                unsigned mwh = (j < 4) ? wh[j] : ((const unsigned*)&h1)[j-4];
                float2 ml = __half22float2(*(const __half2*)&mwl);
                float2 mh = __half22float2(*(const __half2*)&mwh);
                float2 cpv = *(const float2*)&cp[j*8 + t*2];
                sreg[mb][j][0] += ml.x - cpv.x;
                sreg[mb][j][1] += ml.y - cpv.y;
                sreg[mb][j][2] += mh.x - cpv.x;
                sreg[mb][j][3] += mh.y - cpv.y;
            }
        }

        // ---- online softmax + P pack (per m-block) ----
        unsigned ph[2][2][8];   // [mb][lo/hi][j]
        #pragma unroll
        for (int mb = 0; mb < 2; mb++) {
            float tl = -1e30f, th = -1e30f;
            #pragma unroll
            for (int j = 0; j < 8; j++) {
                tl = fmaxf(tl, fmaxf(sreg[mb][j][0], sreg[mb][j][1]));
                th = fmaxf(th, fmaxf(sreg[mb][j][2], sreg[mb][j][3]));
            }
            tl = fmaxf(tl, __shfl_xor_sync(0xffffffffu, tl, 1));
            tl = fmaxf(tl, __shfl_xor_sync(0xffffffffu, tl, 2));
            th = fmaxf(th, __shfl_xor_sync(0xffffffffu, th, 1));
            th = fmaxf(th, __shfl_xor_sync(0xffffffffu, th, 2));
            float mnl = fmaxf(m_st[mb][0], tl), mnh = fmaxf(m_st[mb][1], th);
            float al = exp2f(m_st[mb][0] - mnl), ah = exp2f(m_st[mb][1] - mnh);
            m_st[mb][0] = mnl; m_st[mb][1] = mnh;
            #pragma unroll
            for (int j = 0; j < 8; j++) {
                ph[mb][0][j] = exp2_pack(sreg[mb][j][0] - mnl, sreg[mb][j][1] - mnl);
                ph[mb][1][j] = exp2_pack(sreg[mb][j][2] - mnh, sreg[mb][j][3] - mnh);
                o[mb][j][0] *= al; o[mb][j][1] *= al;
                o[mb][j][2] *= ah; o[mb][j][3] *= ah;
            }
            l_acc[mb][0] *= al; l_acc[mb][1] *= al;
            l_acc[mb][2] *= ah; l_acc[mb][3] *= ah;
        }

        // ---- O += P·V ; l += P·1 (V frags shared across both m-blocks) ----
        #pragma unroll
        for (int jp = 0; jp < 4; jp++) {
            unsigned pa0[4] = { ph[0][0][2*jp], ph[0][1][2*jp],
                                ph[0][0][2*jp+1], ph[0][1][2*jp+1] };
            unsigned pa1[4] = { ph[1][0][2*jp], ph[1][1][2*jp],
                                ph[1][0][2*jp+1], ph[1][1][2*jp+1] };
            #pragma unroll
            for (int np = 0; np < 4; np++) {
                unsigned r0, r1, r2, r3;
                ldsm_x4t(r0, r1, r2, r3,
                         smem_u32(&V[(jp*16 + lrow)*ST + np*16 + lcol]));
                mma_f16(o[0][2*np],     pa0, r0, r1);
                mma_f16(o[0][2*np + 1], pa0, r2, r3);
                mma_f16(o[1][2*np],     pa1, r0, r1);
                mma_f16(o[1][2*np + 1], pa1, r2, r3);
            }
            mma_f16(l_acc[0], pa0, ONE2, ONE2);
            mma_f16(l_acc[1], pa1, ONE2, ONE2);
        }
    }

    // ---- epilogue ----
    #pragma unroll
    for (int mb = 0; mb < 2; mb++) {
        float il = 1.f / l_acc[mb][0], ih = 1.f / l_acc[mb][2];
        int r_lo = q0 + wm + mb*16 + g;
        #pragma unroll
        for (int j = 0; j < 8; j++) {
            float2 v0 = { o[mb][j][0]*il, o[mb][j][1]*il };
            float2 v1 = { o[mb][j][2]*ih, o[mb][j][3]*ih };
            size_t off = ((size_t)b*SEQ + r_lo)*D_MODEL + h*HD + j*8 + t*2;
            *(float2*)&out[off] = v0;
            *(float2*)&out[off + 8*D_MODEL] = v1;
        }
    }
}

// ---------------- launch ----------------
extern "C" void kernel_launch(void* const* d_in, const int* in_sizes, int n_in,
                              void* d_out, int out_size) {
    const float* x      = (const float*)d_in[0];
    const float* coords = (const float*)d_in[1];
    const float* mask   = (const float*)d_in[2];
    const float* qkv_w  = (const float*)d_in[3];
    const float* qkv_b  = (const float*)d_in[4];
    const float* rw     = (const float*)d_in[5];
    float* out = (float*)d_out;

    prep_kernel<<<(PREP_TOT + 255)/256, 256>>>(mask, x, qkv_w, coords, rw);

    cudaFuncSetAttribute(qkv_gemm_kernel,
                         cudaFuncAttributeMaxDynamicSharedMemorySize, G_SMEM);
    dim3 ggrid(3*D_MODEL/64, BATCH*SEQ/128);
    qkv_gemm_kernel<<<ggrid, 256, G_SMEM>>>(qkv_b);

    cudaFuncSetAttribute(flash_kernel,
                         cudaFuncAttributeMaxDynamicSharedMemorySize, F_SMEM);
    dim3 fgrid(SEQ/128, NHEAD, BATCH);
    flash_kernel<<<fgrid, 128, F_SMEM>>>(out);
}